// round 13
// baseline (speedup 1.0000x reference)
#include <cuda_runtime.h>
#include <math.h>
#include <float.h>

// ---------------- constants ----------------
namespace {
constexpr int cS = 2048, cD = 2048, cH = 16, cDN = 128, cDR = 64, cDV = 128;
constexpr int cR = 512, cHI = 4, cDI = 64, cKTOP = 512, cE = 4, cDFF = 8192;
constexpr int cQD  = cH * (cDN + cDR);   // 3072
constexpr int cKVD = cH * (cDN + cDV);   // 4096
}

// ---------------- scratch (static device memory; no allocs allowed) ----------------
__device__ float g_h[cS * cD];
__device__ float g_q[cS * cQD];
__device__ float g_ckv[cS * (cR + cDR)];
__device__ float g_c[cS * cR];
__device__ float g_kv[cS * cKVD];
__device__ float g_krope[cS * cDR];
__device__ float g_qi[cS * cHI * cDI];
__device__ float g_ki[cS * cDI];
__device__ float g_wgt[cS * cHI];
__device__ int   g_topk[cS * cKTOP];
__device__ float g_att[cS * cH * cDV];
__device__ float g_x2[cS * cD];
__device__ float g_h2[cS * cD];
__device__ float g_logits[cS * cE];
__device__ float g_probs[cS * cE];
__device__ int   g_gidx[cS * 2];
__device__ float g_gval[cS * 2];
__device__ int   g_cnt[cE];
__device__ int   g_fill[cE];
__device__ int   g_seg[cE * 2];
__device__ int   g_perm[cS * 2];
__device__ float g_pgate[cS * 2];
__device__ int   g_slot[cS * 2];
__device__ float g_hid[(size_t)cS * 2 * cDFF];   // 4096 x 8192
__device__ float g_eout[(size_t)cS * 2 * cD];    // 4096 x 2048

// ---------------- block reductions ----------------
__device__ __forceinline__ float blockReduceSum(float v) {
    __shared__ float sh[33];
    int lane = threadIdx.x & 31, wid = threadIdx.x >> 5;
#pragma unroll
    for (int o = 16; o; o >>= 1) v += __shfl_down_sync(0xffffffffu, v, o);
    if (lane == 0) sh[wid] = v;
    __syncthreads();
    int nw = (blockDim.x + 31) >> 5;
    v = (threadIdx.x < nw) ? sh[threadIdx.x] : 0.f;
    if (wid == 0) {
#pragma unroll
        for (int o = 16; o; o >>= 1) v += __shfl_down_sync(0xffffffffu, v, o);
        if (lane == 0) sh[32] = v;
    }
    __syncthreads();
    float r = sh[32];
    __syncthreads();
    return r;
}

__device__ __forceinline__ float blockReduceMax(float v) {
    __shared__ float sh[33];
    int lane = threadIdx.x & 31, wid = threadIdx.x >> 5;
#pragma unroll
    for (int o = 16; o; o >>= 1) v = fmaxf(v, __shfl_down_sync(0xffffffffu, v, o));
    if (lane == 0) sh[wid] = v;
    __syncthreads();
    int nw = (blockDim.x + 31) >> 5;
    v = (threadIdx.x < nw) ? sh[threadIdx.x] : -FLT_MAX;
    if (wid == 0) {
#pragma unroll
        for (int o = 16; o; o >>= 1) v = fmaxf(v, __shfl_down_sync(0xffffffffu, v, o));
        if (lane == 0) sh[32] = v;
    }
    __syncthreads();
    float r = sh[32];
    __syncthreads();
    return r;
}

// ---------------- RMSNorm ----------------
__global__ void rms_kernel(const float* __restrict__ in, int instride,
                           const float* __restrict__ w, float* __restrict__ out,
                           int outstride, int cols) {
    int row = blockIdx.x;
    const float* r = in + (size_t)row * instride;
    float ss = 0.f;
    for (int i = threadIdx.x; i < cols; i += blockDim.x) {
        float v = r[i];
        ss += v * v;
    }
    ss = blockReduceSum(ss);
    float scale = rsqrtf(ss / (float)cols + 1e-6f);
    float* o = out + (size_t)row * outstride;
    for (int i = threadIdx.x; i < cols; i += blockDim.x) o[i] = r[i] * scale * w[i];
}

// ---------------- SGEMM (128x128x8, 256 thr, 8x8 per thread) ----------------
// C[start+r, :] = A[rowidx? rowidx[start+r] : start+r, :] @ B  (+ epilogue)
// epi: 0 none; 1 +resid; 2 gelu(.+bias); 3 (.+bias)*rowscale[start+r]
__global__ __launch_bounds__(256) void sgemm_kernel(
    const float* __restrict__ A, const float* __restrict__ B, float* __restrict__ C,
    int M, int N, int K,
    const float* __restrict__ bias, const float* __restrict__ resid,
    const float* __restrict__ rowscale, const int* __restrict__ rowidx,
    const int* __restrict__ seg, int epi) {
    int start = 0, count = M;
    if (seg) { start = seg[0]; count = seg[1]; }
    int m0 = blockIdx.y * 128;
    if (m0 >= count) return;
    int n0 = blockIdx.x * 128;

    __shared__ float As[8][128];
    __shared__ float Bs[8][128];

    int tid  = threadIdx.x;
    int arow = tid >> 1, acol = (tid & 1) << 2;
    int brow = tid >> 5, bcol = (tid & 31) << 2;

    bool aval = (m0 + arow) < count;
    size_t aoff = 0;
    if (aval) {
        int r = rowidx ? rowidx[start + m0 + arow] : (start + m0 + arow);
        aoff = (size_t)r * K + acol;
    }
    bool bval = (n0 + bcol) < N;
    size_t boff = (size_t)brow * N + n0 + bcol;

    int tx = tid & 15, ty = tid >> 4;
    float acc[8][8];
#pragma unroll
    for (int i = 0; i < 8; i++)
#pragma unroll
        for (int j = 0; j < 8; j++) acc[i][j] = 0.f;

    for (int k0 = 0; k0 < K; k0 += 8) {
        float4 av = make_float4(0.f, 0.f, 0.f, 0.f);
        if (aval) av = *(const float4*)(A + aoff + k0);
        float4 bv = make_float4(0.f, 0.f, 0.f, 0.f);
        if (bval) bv = *(const float4*)(B + boff + (size_t)k0 * N);
        As[acol + 0][arow] = av.x;
        As[acol + 1][arow] = av.y;
        As[acol + 2][arow] = av.z;
        As[acol + 3][arow] = av.w;
        *(float4*)&Bs[brow][bcol] = bv;
        __syncthreads();
#pragma unroll
        for (int kk = 0; kk < 8; kk++) {
            float ra[8], rb[8];
            *(float4*)(ra)     = *(const float4*)&As[kk][ty * 8];
            *(float4*)(ra + 4) = *(const float4*)&As[kk][ty * 8 + 4];
            *(float4*)(rb)     = *(const float4*)&Bs[kk][tx * 8];
            *(float4*)(rb + 4) = *(const float4*)&Bs[kk][tx * 8 + 4];
#pragma unroll
            for (int i = 0; i < 8; i++)
#pragma unroll
                for (int j = 0; j < 8; j++) acc[i][j] = fmaf(ra[i], rb[j], acc[i][j]);
        }
        __syncthreads();
    }

#pragma unroll
    for (int i = 0; i < 8; i++) {
        int r = m0 + ty * 8 + i;
        if (r >= count) continue;
        size_t crow = (size_t)(start + r) * N;
        float rs = (epi == 3) ? rowscale[start + r] : 0.f;
#pragma unroll
        for (int j = 0; j < 8; j++) {
            int c = n0 + tx * 8 + j;
            if (c >= N) continue;
            float v = acc[i][j];
            if (epi == 1) {
                v += resid[crow + c];
            } else if (epi == 2) {
                v += bias[c];
                v = 0.5f * v * (1.0f + erff(v * 0.70710678118654752f));
            } else if (epi == 3) {
                v = (v + bias[c]) * rs;
            }
            C[crow + c] = v;
        }
    }
}

// ---------------- RoPE ----------------
__global__ void rope_q_kernel(float* __restrict__ q) {
    int idx = blockIdx.x * blockDim.x + threadIdx.x;  // S*H*32
    if (idx >= cS * cH * 32) return;
    int i  = idx & 31;
    int sh = idx >> 5;
    int h  = sh % cH;
    int s  = sh / cH;
    float freq = (float)(1.0 / pow(10000.0, (double)i / 32.0));
    float ang  = (float)s * freq;
    float cs = cosf(ang), sn = sinf(ang);
    float* base = q + (size_t)s * cQD + h * (cDN + cDR) + cDN;
    float x1 = base[i], x2 = base[i + 32];
    base[i]      = x1 * cs - x2 * sn;
    base[i + 32] = x2 * cs + x1 * sn;
}

__global__ void rope_k_kernel(const float* __restrict__ ckv, float* __restrict__ kr) {
    int idx = blockIdx.x * blockDim.x + threadIdx.x;  // S*32
    if (idx >= cS * 32) return;
    int i = idx & 31;
    int s = idx >> 5;
    float freq = (float)(1.0 / pow(10000.0, (double)i / 32.0));
    float ang  = (float)s * freq;
    float cs = cosf(ang), sn = sinf(ang);
    const float* base = ckv + (size_t)s * (cR + cDR) + cR;
    float x1 = base[i], x2 = base[i + 32];
    kr[(size_t)s * cDR + i]      = x1 * cs - x2 * sn;
    kr[(size_t)s * cDR + i + 32] = x2 * cs + x1 * sn;
}

// ---------------- indexer scores (causal; masked = -FLT_MAX) ----------------
__global__ void idx_kernel(const float* __restrict__ qi, const float* __restrict__ ki,
                           const float* __restrict__ wgt, float* __restrict__ out) {
    int q = blockIdx.y;
    int k = blockIdx.x * 256 + threadIdx.x;
    __shared__ float sq[cHI * cDI];
    __shared__ float sw[cHI];
    sq[threadIdx.x] = qi[(size_t)q * (cHI * cDI) + threadIdx.x];
    if (threadIdx.x < cHI) sw[threadIdx.x] = wgt[q * cHI + threadIdx.x];
    __syncthreads();
    float val;
    if (k > q) {
        val = -FLT_MAX;
    } else {
        const float4* kr = (const float4*)(ki + (size_t)k * cDI);
        float d0 = 0.f, d1 = 0.f, d2 = 0.f, d3 = 0.f;
#pragma unroll
        for (int i = 0; i < 16; i++) {
            float4 v = kr[i];
            int b = 4 * i;
            d0 += sq[b] * v.x + sq[b + 1] * v.y + sq[b + 2] * v.z + sq[b + 3] * v.w;
            d1 += sq[64 + b] * v.x + sq[64 + b + 1] * v.y + sq[64 + b + 2] * v.z + sq[64 + b + 3] * v.w;
            d2 += sq[128 + b] * v.x + sq[128 + b + 1] * v.y + sq[128 + b + 2] * v.z + sq[128 + b + 3] * v.w;
            d3 += sq[192 + b] * v.x + sq[192 + b + 1] * v.y + sq[192 + b + 2] * v.z + sq[192 + b + 3] * v.w;
        }
        val = fmaxf(d0, 0.f) * sw[0] + fmaxf(d1, 0.f) * sw[1] +
              fmaxf(d2, 0.f) * sw[2] + fmaxf(d3, 0.f) * sw[3];
    }
    out[(size_t)q * cS + k] = val;
}

// ---------------- top-k ----------------
__global__ void topk_fill(int* __restrict__ topk) {
    int q = blockIdx.x;  // 0..511 -> all causal prefix kept
    for (int j = threadIdx.x; j <= q; j += blockDim.x) topk[(size_t)q * cKTOP + j] = j;
}

__global__ void topk_radix(const float* __restrict__ scores, int* __restrict__ topk) {
    int q = cKTOP + blockIdx.x;  // 512..2047
    const float* row = scores + (size_t)q * cS;
    int tid = threadIdx.x;  // 256
    unsigned key[8];
#pragma unroll
    for (int j = 0; j < 8; j++) {
        float f = row[tid * 8 + j];
        unsigned b = __float_as_uint(f);
        if (b == 0x80000000u) b = 0u;  // -0 -> +0
        key[j] = (b & 0x80000000u) ? ~b : (b | 0x80000000u);
    }
    __shared__ unsigned hist[256];
    __shared__ unsigned s_pref;
    __shared__ int s_need;
    if (tid == 0) { s_pref = 0; s_need = cKTOP; }
    __syncthreads();
    for (int pass = 0; pass < 4; pass++) {
        hist[tid] = 0;
        __syncthreads();
        unsigned pref = s_pref;
        int shift = 24 - pass * 8;
#pragma unroll
        for (int j = 0; j < 8; j++) {
            unsigned k = key[j];
            bool cand = (pass == 0) ||
                        (((unsigned)((unsigned long long)k >> (shift + 8))) == pref);
            if (cand) atomicAdd(&hist[(k >> shift) & 255u], 1u);
        }
        __syncthreads();
        if (tid == 0) {
            int need = s_need;
            int b = 255;
            while (b > 0 && (int)hist[b] < need) { need -= (int)hist[b]; b--; }
            s_pref = (pref << 8) | (unsigned)b;
            s_need = need;
        }
        __syncthreads();
    }
    unsigned thr = s_pref;
    int needEq = s_need;
    __shared__ int s_gt;
    if (tid == 0) s_gt = 0;
    __syncthreads();
    int* orow = topk + (size_t)q * cKTOP;
#pragma unroll
    for (int j = 0; j < 8; j++) {
        if (key[j] > thr) {
            int p = atomicAdd(&s_gt, 1);
            orow[p] = tid * 8 + j;
        }
    }
    __syncthreads();
    int base = s_gt;  // = cKTOP - needEq
    int myc = 0;
#pragma unroll
    for (int j = 0; j < 8; j++) myc += (key[j] == thr);
    __shared__ int sscan[256];
    sscan[tid] = myc;
    __syncthreads();
    for (int off = 1; off < 256; off <<= 1) {
        int v = (tid >= off) ? sscan[tid - off] : 0;
        __syncthreads();
        sscan[tid] += v;
        __syncthreads();
    }
    int r = sscan[tid] - myc;
#pragma unroll
    for (int j = 0; j < 8; j++) {
        if (key[j] == thr) {
            if (r < needEq) orow[base + r] = tid * 8 + j;
            r++;
        }
    }
}

// ---------------- sparse attention ----------------
__global__ void attn_kernel(const float* __restrict__ q, const float* __restrict__ kv,
                            const float* __restrict__ kr, const int* __restrict__ topk,
                            float* __restrict__ out) {
    int qr = blockIdx.x;
    int h  = blockIdx.y;
    int cnt = min(qr + 1, cKTOP);
    __shared__ float sq[192];
    __shared__ float sc[cKTOP];
    int tid = threadIdx.x;  // 256
    if (tid < 192) sq[tid] = q[(size_t)qr * cQD + h * 192 + tid];
    __syncthreads();
    const int* tk = topk + (size_t)qr * cKTOP;
    for (int j = tid; j < cnt; j += 256) {
        int k = tk[j];
        const float4* kn = (const float4*)(kv + (size_t)k * cKVD + h * (cDN + cDV));
        float d = 0.f;
#pragma unroll
        for (int i = 0; i < 32; i++) {
            float4 v = kn[i];
            int b = 4 * i;
            d += sq[b] * v.x + sq[b + 1] * v.y + sq[b + 2] * v.z + sq[b + 3] * v.w;
        }
        const float4* krp = (const float4*)(kr + (size_t)k * cDR);
#pragma unroll
        for (int i = 0; i < 16; i++) {
            float4 v = krp[i];
            int b = 128 + 4 * i;
            d += sq[b] * v.x + sq[b + 1] * v.y + sq[b + 2] * v.z + sq[b + 3] * v.w;
        }
        sc[j] = d * 0.07216878364870323f;  // 1/sqrt(192)
    }
    __syncthreads();
    float m = -FLT_MAX;
    for (int j = tid; j < cnt; j += 256) m = fmaxf(m, sc[j]);
    m = blockReduceMax(m);
    float ls = 0.f;
    for (int j = tid; j < cnt; j += 256) {
        float e = expf(sc[j] - m);
        sc[j] = e;
        ls += e;
    }
    __syncthreads();
    float ssum = blockReduceSum(ls);
    float inv = 1.0f / ssum;
    if (tid < cDV) {
        float acc = 0.f;
        for (int j = 0; j < cnt; j++) {
            int k = tk[j];
            acc += sc[j] * kv[(size_t)k * cKVD + h * (cDN + cDV) + cDN + tid];
        }
        out[(size_t)qr * (cH * cDV) + h * cDV + tid] = acc * inv;
    }
}

// ---------------- router / MoE bookkeeping ----------------
__global__ void reset_kernel(int* __restrict__ cnt) {
    if (threadIdx.x < cE) cnt[threadIdx.x] = 0;
}

__global__ void router_kernel(const float* __restrict__ logits, float* __restrict__ probs,
                              int* __restrict__ gidx, float* __restrict__ gval,
                              int* __restrict__ cnt) {
    int t = blockIdx.x * blockDim.x + threadIdx.x;
    if (t >= cS) return;
    float l[cE];
#pragma unroll
    for (int e = 0; e < cE; e++) l[e] = logits[t * cE + e];
    float m = l[0];
#pragma unroll
    for (int e = 1; e < cE; e++) m = fmaxf(m, l[e]);
    float ex[cE], s = 0.f;
#pragma unroll
    for (int e = 0; e < cE; e++) { ex[e] = expf(l[e] - m); s += ex[e]; }
    float p[cE];
#pragma unroll
    for (int e = 0; e < cE; e++) { p[e] = ex[e] / s; probs[t * cE + e] = p[e]; }
    int e0 = 0;
#pragma unroll
    for (int e = 1; e < cE; e++) if (p[e] > p[e0]) e0 = e;
    int e1 = -1;
#pragma unroll
    for (int e = 0; e < cE; e++) {
        if (e == e0) continue;
        if (e1 < 0 || p[e] > p[e1]) e1 = e;
    }
    float g0 = p[e0], g1 = p[e1];
    float invg = 1.0f / (g0 + g1);
    gidx[t * 2] = e0; gidx[t * 2 + 1] = e1;
    gval[t * 2] = g0 * invg; gval[t * 2 + 1] = g1 * invg;
    atomicAdd(&cnt[e0], 1);
    atomicAdd(&cnt[e1], 1);
}

__global__ void seg_kernel(const int* __restrict__ cnt, int* __restrict__ seg,
                           int* __restrict__ fill) {
    if (threadIdx.x == 0) {
        int off = 0;
        for (int e = 0; e < cE; e++) {
            seg[2 * e] = off;
            seg[2 * e + 1] = cnt[e];
            off += cnt[e];
            fill[e] = 0;
        }
    }
}

__global__ void place_kernel(const int* __restrict__ gidx, const float* __restrict__ gval,
                             const int* __restrict__ seg, int* __restrict__ fill,
                             int* __restrict__ perm, float* __restrict__ pgate,
                             int* __restrict__ slot) {
    int t = blockIdx.x * blockDim.x + threadIdx.x;
    if (t >= cS) return;
    for (int s2 = 0; s2 < 2; s2++) {
        int e = gidx[t * 2 + s2];
        int pos = seg[2 * e] + atomicAdd(&fill[e], 1);
        perm[pos] = t;
        pgate[pos] = gval[t * 2 + s2];
        slot[t * 2 + s2] = pos;
    }
}

__global__ void combine_kernel(const float* __restrict__ x2, const float* __restrict__ eout,
                               const int* __restrict__ slot, float* __restrict__ out) {
    int idx = blockIdx.x * blockDim.x + threadIdx.x;
    if (idx >= cS * cD) return;
    int t = idx >> 11;  // /2048
    int d = idx & 2047;
    out[idx] = x2[idx] + eout[(size_t)slot[t * 2] * cD + d] +
               eout[(size_t)slot[t * 2 + 1] * cD + d];
}

__global__ void aux_kernel(const float* __restrict__ probs, const int* __restrict__ cnt,
                           float* __restrict__ out_aux) {
    float a0 = 0.f, a1 = 0.f, a2 = 0.f, a3 = 0.f;
    for (int t = threadIdx.x; t < cS; t += blockDim.x) {
        a0 += probs[t * cE + 0];
        a1 += probs[t * cE + 1];
        a2 += probs[t * cE + 2];
        a3 += probs[t * cE + 3];
    }
    float s0 = blockReduceSum(a0);
    float s1 = blockReduceSum(a1);
    float s2 = blockReduceSum(a2);
    float s3 = blockReduceSum(a3);
    if (threadIdx.x == 0) {
        float P[4] = {s0 / cS, s1 / cS, s2 / cS, s3 / cS};
        float aux = 0.f;
        for (int e = 0; e < cE; e++) aux += ((float)cnt[e] / (float)cS) * P[e];
        *out_aux = (float)cE * aux;
    }
}

// ---------------- host launch ----------------
static void gemm(const float* A, const float* B, float* C, int M, int N, int K,
                 const float* bias, const float* resid, const float* rowscale,
                 const int* rowidx, const int* seg, int epi) {
    dim3 g((N + 127) / 128, (M + 127) / 128);
    sgemm_kernel<<<g, 256>>>(A, B, C, M, N, K, bias, resid, rowscale, rowidx, seg, epi);
}

extern "C" void kernel_launch(void* const* d_in, const int* in_sizes, int n_in,
                              void* d_out, int out_size) {
    const float* x    = (const float*)d_in[0];
    const float* n1w  = (const float*)d_in[1];
    const float* n2w  = (const float*)d_in[2];
    const float* kvnw = (const float*)d_in[3];
    const float* Wq   = (const float*)d_in[4];
    const float* Wkva = (const float*)d_in[5];
    const float* Wkvb = (const float*)d_in[6];
    const float* Wo   = (const float*)d_in[7];
    const float* Wiq  = (const float*)d_in[8];
    const float* Wik  = (const float*)d_in[9];
    const float* Wiw  = (const float*)d_in[10];
    const float* Wr   = (const float*)d_in[11];
    const float* W1   = (const float*)d_in[12];
    const float* b1   = (const float*)d_in[13];
    const float* W2   = (const float*)d_in[14];
    const float* b2   = (const float*)d_in[15];

    float* out     = (float*)d_out;
    float* out_x   = out;
    float* out_aux = out + (size_t)cS * cD;
    float* out_idx = out + (size_t)cS * cD + 1;

    void* pv;
    cudaGetSymbolAddress(&pv, g_h);      float* ph     = (float*)pv;
    cudaGetSymbolAddress(&pv, g_q);      float* pq     = (float*)pv;
    cudaGetSymbolAddress(&pv, g_ckv);    float* pckv   = (float*)pv;
    cudaGetSymbolAddress(&pv, g_c);      float* pc     = (float*)pv;
    cudaGetSymbolAddress(&pv, g_kv);     float* pkv    = (float*)pv;
    cudaGetSymbolAddress(&pv, g_krope);  float* pkr    = (float*)pv;
    cudaGetSymbolAddress(&pv, g_qi);     float* pqi    = (float*)pv;
    cudaGetSymbolAddress(&pv, g_ki);     float* pki    = (float*)pv;
    cudaGetSymbolAddress(&pv, g_wgt);    float* pwgt   = (float*)pv;
    cudaGetSymbolAddress(&pv, g_topk);   int*   ptopk  = (int*)pv;
    cudaGetSymbolAddress(&pv, g_att);    float* patt   = (float*)pv;
    cudaGetSymbolAddress(&pv, g_x2);     float* px2    = (float*)pv;
    cudaGetSymbolAddress(&pv, g_h2);     float* ph2    = (float*)pv;
    cudaGetSymbolAddress(&pv, g_logits); float* plog   = (float*)pv;
    cudaGetSymbolAddress(&pv, g_probs);  float* pprob  = (float*)pv;
    cudaGetSymbolAddress(&pv, g_gidx);   int*   pgidx  = (int*)pv;
    cudaGetSymbolAddress(&pv, g_gval);   float* pgval  = (float*)pv;
    cudaGetSymbolAddress(&pv, g_cnt);    int*   pcnt   = (int*)pv;
    cudaGetSymbolAddress(&pv, g_fill);   int*   pfill  = (int*)pv;
    cudaGetSymbolAddress(&pv, g_seg);    int*   pseg   = (int*)pv;
    cudaGetSymbolAddress(&pv, g_perm);   int*   pperm  = (int*)pv;
    cudaGetSymbolAddress(&pv, g_pgate);  float* ppg    = (float*)pv;
    cudaGetSymbolAddress(&pv, g_slot);   int*   pslot  = (int*)pv;
    cudaGetSymbolAddress(&pv, g_hid);    float* phid   = (float*)pv;
    cudaGetSymbolAddress(&pv, g_eout);   float* peout  = (float*)pv;

    // 1) h = rms(x)
    rms_kernel<<<cS, 256>>>(x, cD, n1w, ph, cD, cD);
    // 2) q = h @ Wq
    gemm(ph, Wq, pq, cS, cQD, cD, nullptr, nullptr, nullptr, nullptr, nullptr, 0);
    // 3) ckv = h @ Wkva
    gemm(ph, Wkva, pckv, cS, cR + cDR, cD, nullptr, nullptr, nullptr, nullptr, nullptr, 0);
    // 4) c = rms(ckv[:, :R])
    rms_kernel<<<cS, 256>>>(pckv, cR + cDR, kvnw, pc, cR, cR);
    // 5) kv = c @ Wkvb
    gemm(pc, Wkvb, pkv, cS, cKVD, cR, nullptr, nullptr, nullptr, nullptr, nullptr, 0);
    // 6) rope
    rope_q_kernel<<<(cS * cH * 32 + 255) / 256, 256>>>(pq);
    rope_k_kernel<<<(cS * 32 + 255) / 256, 256>>>(pckv, pkr);
    // 7) indexer projections
    gemm(ph, Wiq, pqi, cS, cHI * cDI, cD, nullptr, nullptr, nullptr, nullptr, nullptr, 0);
    gemm(ph, Wik, pki, cS, cDI, cD, nullptr, nullptr, nullptr, nullptr, nullptr, 0);
    gemm(ph, Wiw, pwgt, cS, cHI, cD, nullptr, nullptr, nullptr, nullptr, nullptr, 0);
    // 8) idx scores (-> output region)
    idx_kernel<<<dim3(cS / 256, cS), 256>>>(pqi, pki, pwgt, out_idx);
    // 9) top-k select
    topk_fill<<<cKTOP, 256>>>(ptopk);
    topk_radix<<<cS - cKTOP, 256>>>(out_idx, ptopk);
    // 10) sparse attention
    attn_kernel<<<dim3(cS, cH), 256>>>(pq, pkv, pkr, ptopk, patt);
    // 11) x2 = x + att @ Wo
    gemm(patt, Wo, px2, cS, cD, cH * cDV, nullptr, x, nullptr, nullptr, nullptr, 1);
    // 12) h2 = rms(x2)
    rms_kernel<<<cS, 256>>>(px2, cD, n2w, ph2, cD, cD);
    // 13) router logits
    gemm(ph2, Wr, plog, cS, cE, cD, nullptr, nullptr, nullptr, nullptr, nullptr, 0);
    // 14) router softmax/top2/count
    reset_kernel<<<1, 32>>>(pcnt);
    router_kernel<<<(cS + 255) / 256, 256>>>(plog, pprob, pgidx, pgval, pcnt);
    seg_kernel<<<1, 32>>>(pcnt, pseg, pfill);
    place_kernel<<<(cS + 255) / 256, 256>>>(pgidx, pgval, pseg, pfill, pperm, ppg, pslot);
    // 15) MoE expert GEMMs (gathered rows, segment-dynamic M)
    for (int e = 0; e < cE; e++) {
        gemm(ph2, W1 + (size_t)e * cD * cDFF, phid, cS, cDFF, cD,
             b1 + (size_t)e * cDFF, nullptr, nullptr, pperm, pseg + 2 * e, 2);
        gemm(phid, W2 + (size_t)e * cDFF * cD, peout, cS, cD, cDFF,
             b2 + (size_t)e * cD, nullptr, ppg, nullptr, pseg + 2 * e, 3);
    }
    // 16) final residual combine -> output x
    combine_kernel<<<(cS * cD + 255) / 256, 256>>>(px2, peout, pslot, out_x);
    // 17) aux loss -> output scalar
    aux_kernel<<<1, 256>>>(pprob, pcnt, out_aux);
}

// round 14
// speedup vs baseline: 1.0042x; 1.0042x over previous
#include <cuda_runtime.h>
#include <math.h>
#include <float.h>

// ---------------- constants ----------------
namespace {
constexpr int cS = 2048, cD = 2048, cH = 16, cDN = 128, cDR = 64, cDV = 128;
constexpr int cR = 512, cHI = 4, cDI = 64, cKTOP = 512, cE = 4, cDFF = 8192;
constexpr int cQD  = cH * (cDN + cDR);   // 3072
constexpr int cKVD = cH * (cDN + cDV);   // 4096
}

// ---------------- scratch (static device memory; no allocs allowed) ----------------
__device__ float g_h[cS * cD];
__device__ float g_q[cS * cQD];
__device__ float g_ckv[cS * (cR + cDR)];
__device__ float g_c[cS * cR];
__device__ float g_kv[cS * cKVD];
__device__ float g_krope[cS * cDR];
__device__ float g_qi[cS * cHI * cDI];
__device__ float g_ki[cS * cDI];
__device__ float g_wgt[cS * cHI];
__device__ int   g_topk[cS * cKTOP];
__device__ float g_att[cS * cH * cDV];
__device__ float g_x2[cS * cD];
__device__ float g_h2[cS * cD];
__device__ float g_logits[cS * cE];
__device__ float g_probs[cS * cE];
__device__ int   g_gidx[cS * 2];
__device__ float g_gval[cS * 2];
__device__ int   g_cnt[cE];
__device__ int   g_fill[cE];
__device__ int   g_seg[cE * 2];
__device__ int   g_perm[cS * 2];
__device__ float g_pgate[cS * 2];
__device__ int   g_slot[cS * 2];
__device__ float g_hid[(size_t)cS * 2 * cDFF];   // 4096 x 8192
__device__ float g_eout[(size_t)cS * 2 * cD];    // 4096 x 2048

// ---------------- block reductions ----------------
__device__ __forceinline__ float blockReduceSum(float v) {
    __shared__ float sh[33];
    int lane = threadIdx.x & 31, wid = threadIdx.x >> 5;
#pragma unroll
    for (int o = 16; o; o >>= 1) v += __shfl_down_sync(0xffffffffu, v, o);
    if (lane == 0) sh[wid] = v;
    __syncthreads();
    int nw = (blockDim.x + 31) >> 5;
    v = (threadIdx.x < nw) ? sh[threadIdx.x] : 0.f;
    if (wid == 0) {
#pragma unroll
        for (int o = 16; o; o >>= 1) v += __shfl_down_sync(0xffffffffu, v, o);
        if (lane == 0) sh[32] = v;
    }
    __syncthreads();
    float r = sh[32];
    __syncthreads();
    return r;
}

__device__ __forceinline__ float blockReduceMax(float v) {
    __shared__ float sh[33];
    int lane = threadIdx.x & 31, wid = threadIdx.x >> 5;
#pragma unroll
    for (int o = 16; o; o >>= 1) v = fmaxf(v, __shfl_down_sync(0xffffffffu, v, o));
    if (lane == 0) sh[wid] = v;
    __syncthreads();
    int nw = (blockDim.x + 31) >> 5;
    v = (threadIdx.x < nw) ? sh[threadIdx.x] : -FLT_MAX;
    if (wid == 0) {
#pragma unroll
        for (int o = 16; o; o >>= 1) v = fmaxf(v, __shfl_down_sync(0xffffffffu, v, o));
        if (lane == 0) sh[32] = v;
    }
    __syncthreads();
    float r = sh[32];
    __syncthreads();
    return r;
}

// ---------------- RMSNorm ----------------
__global__ void rms_kernel(const float* __restrict__ in, int instride,
                           const float* __restrict__ w, float* __restrict__ out,
                           int outstride, int cols) {
    int row = blockIdx.x;
    const float* r = in + (size_t)row * instride;
    float ss = 0.f;
    for (int i = threadIdx.x; i < cols; i += blockDim.x) {
        float v = r[i];
        ss += v * v;
    }
    ss = blockReduceSum(ss);
    float scale = rsqrtf(ss / (float)cols + 1e-6f);
    float* o = out + (size_t)row * outstride;
    for (int i = threadIdx.x; i < cols; i += blockDim.x) o[i] = r[i] * scale * w[i];
}

// ---------------- SGEMM (128x128x8, 256 thr, 8x8 per thread) ----------------
// C[start+r, :] = A[rowidx? rowidx[start+r] : start+r, :] @ B  (+ epilogue)
// epi: 0 none; 1 +resid; 2 gelu(.+bias); 3 (.+bias)*rowscale[start+r]
__global__ __launch_bounds__(256) void sgemm_kernel(
    const float* __restrict__ A, const float* __restrict__ B, float* __restrict__ C,
    int M, int N, int K,
    const float* __restrict__ bias, const float* __restrict__ resid,
    const float* __restrict__ rowscale, const int* __restrict__ rowidx,
    const int* __restrict__ seg, int epi) {
    int start = 0, count = M;
    if (seg) { start = seg[0]; count = seg[1]; }
    int m0 = blockIdx.y * 128;
    if (m0 >= count) return;
    int n0 = blockIdx.x * 128;

    __shared__ float As[8][128];
    __shared__ float Bs[8][128];

    int tid  = threadIdx.x;
    int arow = tid >> 1, acol = (tid & 1) << 2;
    int brow = tid >> 5, bcol = (tid & 31) << 2;

    bool aval = (m0 + arow) < count;
    size_t aoff = 0;
    if (aval) {
        int r = rowidx ? rowidx[start + m0 + arow] : (start + m0 + arow);
        aoff = (size_t)r * K + acol;
    }
    bool bval = (n0 + bcol) < N;
    size_t boff = (size_t)brow * N + n0 + bcol;

    int tx = tid & 15, ty = tid >> 4;
    float acc[8][8];
#pragma unroll
    for (int i = 0; i < 8; i++)
#pragma unroll
        for (int j = 0; j < 8; j++) acc[i][j] = 0.f;

    for (int k0 = 0; k0 < K; k0 += 8) {
        float4 av = make_float4(0.f, 0.f, 0.f, 0.f);
        if (aval) av = *(const float4*)(A + aoff + k0);
        float4 bv = make_float4(0.f, 0.f, 0.f, 0.f);
        if (bval) bv = *(const float4*)(B + boff + (size_t)k0 * N);
        As[acol + 0][arow] = av.x;
        As[acol + 1][arow] = av.y;
        As[acol + 2][arow] = av.z;
        As[acol + 3][arow] = av.w;
        *(float4*)&Bs[brow][bcol] = bv;
        __syncthreads();
#pragma unroll
        for (int kk = 0; kk < 8; kk++) {
            float ra[8], rb[8];
            *(float4*)(ra)     = *(const float4*)&As[kk][ty * 8];
            *(float4*)(ra + 4) = *(const float4*)&As[kk][ty * 8 + 4];
            *(float4*)(rb)     = *(const float4*)&Bs[kk][tx * 8];
            *(float4*)(rb + 4) = *(const float4*)&Bs[kk][tx * 8 + 4];
#pragma unroll
            for (int i = 0; i < 8; i++)
#pragma unroll
                for (int j = 0; j < 8; j++) acc[i][j] = fmaf(ra[i], rb[j], acc[i][j]);
        }
        __syncthreads();
    }

#pragma unroll
    for (int i = 0; i < 8; i++) {
        int r = m0 + ty * 8 + i;
        if (r >= count) continue;
        size_t crow = (size_t)(start + r) * N;
        float rs = (epi == 3) ? rowscale[start + r] : 0.f;
#pragma unroll
        for (int j = 0; j < 8; j++) {
            int c = n0 + tx * 8 + j;
            if (c >= N) continue;
            float v = acc[i][j];
            if (epi == 1) {
                v += resid[crow + c];
            } else if (epi == 2) {
                v += bias[c];
                v = 0.5f * v * (1.0f + erff(v * 0.70710678118654752f));
            } else if (epi == 3) {
                v = (v + bias[c]) * rs;
            }
            C[crow + c] = v;
        }
    }
}

// ---------------- RoPE ----------------
__global__ void rope_q_kernel(float* __restrict__ q) {
    int idx = blockIdx.x * blockDim.x + threadIdx.x;  // S*H*32
    if (idx >= cS * cH * 32) return;
    int i  = idx & 31;
    int sh = idx >> 5;
    int h  = sh % cH;
    int s  = sh / cH;
    float freq = (float)(1.0 / pow(10000.0, (double)i / 32.0));
    float ang  = (float)s * freq;
    float cs = cosf(ang), sn = sinf(ang);
    float* base = q + (size_t)s * cQD + h * (cDN + cDR) + cDN;
    float x1 = base[i], x2 = base[i + 32];
    base[i]      = x1 * cs - x2 * sn;
    base[i + 32] = x2 * cs + x1 * sn;
}

__global__ void rope_k_kernel(const float* __restrict__ ckv, float* __restrict__ kr) {
    int idx = blockIdx.x * blockDim.x + threadIdx.x;  // S*32
    if (idx >= cS * 32) return;
    int i = idx & 31;
    int s = idx >> 5;
    float freq = (float)(1.0 / pow(10000.0, (double)i / 32.0));
    float ang  = (float)s * freq;
    float cs = cosf(ang), sn = sinf(ang);
    const float* base = ckv + (size_t)s * (cR + cDR) + cR;
    float x1 = base[i], x2 = base[i + 32];
    kr[(size_t)s * cDR + i]      = x1 * cs - x2 * sn;
    kr[(size_t)s * cDR + i + 32] = x2 * cs + x1 * sn;
}

// ---------------- indexer scores (causal; masked = -FLT_MAX) ----------------
__global__ void idx_kernel(const float* __restrict__ qi, const float* __restrict__ ki,
                           const float* __restrict__ wgt, float* __restrict__ out) {
    int q = blockIdx.y;
    int k = blockIdx.x * 256 + threadIdx.x;
    __shared__ float sq[cHI * cDI];
    __shared__ float sw[cHI];
    sq[threadIdx.x] = qi[(size_t)q * (cHI * cDI) + threadIdx.x];
    if (threadIdx.x < cHI) sw[threadIdx.x] = wgt[q * cHI + threadIdx.x];
    __syncthreads();
    float val;
    if (k > q) {
        val = -FLT_MAX;
    } else {
        const float4* kr = (const float4*)(ki + (size_t)k * cDI);
        float d0 = 0.f, d1 = 0.f, d2 = 0.f, d3 = 0.f;
#pragma unroll
        for (int i = 0; i < 16; i++) {
            float4 v = kr[i];
            int b = 4 * i;
            d0 += sq[b] * v.x + sq[b + 1] * v.y + sq[b + 2] * v.z + sq[b + 3] * v.w;
            d1 += sq[64 + b] * v.x + sq[64 + b + 1] * v.y + sq[64 + b + 2] * v.z + sq[64 + b + 3] * v.w;
            d2 += sq[128 + b] * v.x + sq[128 + b + 1] * v.y + sq[128 + b + 2] * v.z + sq[128 + b + 3] * v.w;
            d3 += sq[192 + b] * v.x + sq[192 + b + 1] * v.y + sq[192 + b + 2] * v.z + sq[192 + b + 3] * v.w;
        }
        val = fmaxf(d0, 0.f) * sw[0] + fmaxf(d1, 0.f) * sw[1] +
              fmaxf(d2, 0.f) * sw[2] + fmaxf(d3, 0.f) * sw[3];
    }
    out[(size_t)q * cS + k] = val;
}

// ---------------- top-k ----------------
__global__ void topk_fill(int* __restrict__ topk) {
    int q = blockIdx.x;  // 0..511 -> all causal prefix kept
    for (int j = threadIdx.x; j <= q; j += blockDim.x) topk[(size_t)q * cKTOP + j] = j;
}

__global__ void topk_radix(const float* __restrict__ scores, int* __restrict__ topk) {
    int q = cKTOP + blockIdx.x;  // 512..2047
    const float* row = scores + (size_t)q * cS;
    int tid = threadIdx.x;  // 256
    unsigned key[8];
#pragma unroll
    for (int j = 0; j < 8; j++) {
        float f = row[tid * 8 + j];
        unsigned b = __float_as_uint(f);
        if (b == 0x80000000u) b = 0u;  // -0 -> +0
        key[j] = (b & 0x80000000u) ? ~b : (b | 0x80000000u);
    }
    __shared__ unsigned hist[256];
    __shared__ unsigned s_pref;
    __shared__ int s_need;
    if (tid == 0) { s_pref = 0; s_need = cKTOP; }
    __syncthreads();
    for (int pass = 0; pass < 4; pass++) {
        hist[tid] = 0;
        __syncthreads();
        unsigned pref = s_pref;
        int shift = 24 - pass * 8;
#pragma unroll
        for (int j = 0; j < 8; j++) {
            unsigned k = key[j];
            bool cand = (pass == 0) ||
                        (((unsigned)((unsigned long long)k >> (shift + 8))) == pref);
            if (cand) atomicAdd(&hist[(k >> shift) & 255u], 1u);
        }
        __syncthreads();
        if (tid == 0) {
            int need = s_need;
            int b = 255;
            while (b > 0 && (int)hist[b] < need) { need -= (int)hist[b]; b--; }
            s_pref = (pref << 8) | (unsigned)b;
            s_need = need;
        }
        __syncthreads();
    }
    unsigned thr = s_pref;
    int needEq = s_need;
    __shared__ int s_gt;
    if (tid == 0) s_gt = 0;
    __syncthreads();
    int* orow = topk + (size_t)q * cKTOP;
#pragma unroll
    for (int j = 0; j < 8; j++) {
        if (key[j] > thr) {
            int p = atomicAdd(&s_gt, 1);
            orow[p] = tid * 8 + j;
        }
    }
    __syncthreads();
    int base = s_gt;  // = cKTOP - needEq
    int myc = 0;
#pragma unroll
    for (int j = 0; j < 8; j++) myc += (key[j] == thr);
    __shared__ int sscan[256];
    sscan[tid] = myc;
    __syncthreads();
    for (int off = 1; off < 256; off <<= 1) {
        int v = (tid >= off) ? sscan[tid - off] : 0;
        __syncthreads();
        sscan[tid] += v;
        __syncthreads();
    }
    int r = sscan[tid] - myc;
#pragma unroll
    for (int j = 0; j < 8; j++) {
        if (key[j] == thr) {
            if (r < needEq) orow[base + r] = tid * 8 + j;
            r++;
        }
    }
}

// ---------------- sparse attention ----------------
__global__ void attn_kernel(const float* __restrict__ q, const float* __restrict__ kv,
                            const float* __restrict__ kr, const int* __restrict__ topk,
                            float* __restrict__ out) {
    int qr = blockIdx.x;
    int h  = blockIdx.y;
    int cnt = min(qr + 1, cKTOP);
    __shared__ float sq[192];
    __shared__ float sc[cKTOP];
    int tid = threadIdx.x;  // 256
    if (tid < 192) sq[tid] = q[(size_t)qr * cQD + h * 192 + tid];
    __syncthreads();
    const int* tk = topk + (size_t)qr * cKTOP;
    for (int j = tid; j < cnt; j += 256) {
        int k = tk[j];
        const float4* kn = (const float4*)(kv + (size_t)k * cKVD + h * (cDN + cDV));
        float d = 0.f;
#pragma unroll
        for (int i = 0; i < 32; i++) {
            float4 v = kn[i];
            int b = 4 * i;
            d += sq[b] * v.x + sq[b + 1] * v.y + sq[b + 2] * v.z + sq[b + 3] * v.w;
        }
        const float4* krp = (const float4*)(kr + (size_t)k * cDR);
#pragma unroll
        for (int i = 0; i < 16; i++) {
            float4 v = krp[i];
            int b = 128 + 4 * i;
            d += sq[b] * v.x + sq[b + 1] * v.y + sq[b + 2] * v.z + sq[b + 3] * v.w;
        }
        sc[j] = d * 0.07216878364870323f;  // 1/sqrt(192)
    }
    __syncthreads();
    float m = -FLT_MAX;
    for (int j = tid; j < cnt; j += 256) m = fmaxf(m, sc[j]);
    m = blockReduceMax(m);
    float ls = 0.f;
    for (int j = tid; j < cnt; j += 256) {
        float e = expf(sc[j] - m);
        sc[j] = e;
        ls += e;
    }
    __syncthreads();
    float ssum = blockReduceSum(ls);
    float inv = 1.0f / ssum;
    if (tid < cDV) {
        float acc = 0.f;
        for (int j = 0; j < cnt; j++) {
            int k = tk[j];
            acc += sc[j] * kv[(size_t)k * cKVD + h * (cDN + cDV) + cDN + tid];
        }
        out[(size_t)qr * (cH * cDV) + h * cDV + tid] = acc * inv;
    }
}

// ---------------- router / MoE bookkeeping ----------------
__global__ void reset_kernel(int* __restrict__ cnt) {
    if (threadIdx.x < cE) cnt[threadIdx.x] = 0;
}

__global__ void router_kernel(const float* __restrict__ logits, float* __restrict__ probs,
                              int* __restrict__ gidx, float* __restrict__ gval,
                              int* __restrict__ cnt) {
    int t = blockIdx.x * blockDim.x + threadIdx.x;
    if (t >= cS) return;
    float l[cE];
#pragma unroll
    for (int e = 0; e < cE; e++) l[e] = logits[t * cE + e];
    float m = l[0];
#pragma unroll
    for (int e = 1; e < cE; e++) m = fmaxf(m, l[e]);
    float ex[cE], s = 0.f;
#pragma unroll
    for (int e = 0; e < cE; e++) { ex[e] = expf(l[e] - m); s += ex[e]; }
    float p[cE];
#pragma unroll
    for (int e = 0; e < cE; e++) { p[e] = ex[e] / s; probs[t * cE + e] = p[e]; }
    int e0 = 0;
#pragma unroll
    for (int e = 1; e < cE; e++) if (p[e] > p[e0]) e0 = e;
    int e1 = -1;
#pragma unroll
    for (int e = 0; e < cE; e++) {
        if (e == e0) continue;
        if (e1 < 0 || p[e] > p[e1]) e1 = e;
    }
    float g0 = p[e0], g1 = p[e1];
    float invg = 1.0f / (g0 + g1);
    gidx[t * 2] = e0; gidx[t * 2 + 1] = e1;
    gval[t * 2] = g0 * invg; gval[t * 2 + 1] = g1 * invg;
    atomicAdd(&cnt[e0], 1);
    atomicAdd(&cnt[e1], 1);
}

__global__ void seg_kernel(const int* __restrict__ cnt, int* __restrict__ seg,
                           int* __restrict__ fill) {
    if (threadIdx.x == 0) {
        int off = 0;
        for (int e = 0; e < cE; e++) {
            seg[2 * e] = off;
            seg[2 * e + 1] = cnt[e];
            off += cnt[e];
            fill[e] = 0;
        }
    }
}

__global__ void place_kernel(const int* __restrict__ gidx, const float* __restrict__ gval,
                             const int* __restrict__ seg, int* __restrict__ fill,
                             int* __restrict__ perm, float* __restrict__ pgate,
                             int* __restrict__ slot) {
    int t = blockIdx.x * blockDim.x + threadIdx.x;
    if (t >= cS) return;
    for (int s2 = 0; s2 < 2; s2++) {
        int e = gidx[t * 2 + s2];
        int pos = seg[2 * e] + atomicAdd(&fill[e], 1);
        perm[pos] = t;
        pgate[pos] = gval[t * 2 + s2];
        slot[t * 2 + s2] = pos;
    }
}

__global__ void combine_kernel(const float* __restrict__ x2, const float* __restrict__ eout,
                               const int* __restrict__ slot, float* __restrict__ out) {
    int idx = blockIdx.x * blockDim.x + threadIdx.x;
    if (idx >= cS * cD) return;
    int t = idx >> 11;  // /2048
    int d = idx & 2047;
    out[idx] = x2[idx] + eout[(size_t)slot[t * 2] * cD + d] +
               eout[(size_t)slot[t * 2 + 1] * cD + d];
}

__global__ void aux_kernel(const float* __restrict__ probs, const int* __restrict__ cnt,
                           float* __restrict__ out_aux) {
    float a0 = 0.f, a1 = 0.f, a2 = 0.f, a3 = 0.f;
    for (int t = threadIdx.x; t < cS; t += blockDim.x) {
        a0 += probs[t * cE + 0];
        a1 += probs[t * cE + 1];
        a2 += probs[t * cE + 2];
        a3 += probs[t * cE + 3];
    }
    float s0 = blockReduceSum(a0);
    float s1 = blockReduceSum(a1);
    float s2 = blockReduceSum(a2);
    float s3 = blockReduceSum(a3);
    if (threadIdx.x == 0) {
        float P[4] = {s0 / cS, s1 / cS, s2 / cS, s3 / cS};
        float aux = 0.f;
        for (int e = 0; e < cE; e++) aux += ((float)cnt[e] / (float)cS) * P[e];
        *out_aux = (float)cE * aux;
    }
}

// ---------------- host launch ----------------
static void gemm(const float* A, const float* B, float* C, int M, int N, int K,
                 const float* bias, const float* resid, const float* rowscale,
                 const int* rowidx, const int* seg, int epi) {
    dim3 g((N + 127) / 128, (M + 127) / 128);
    sgemm_kernel<<<g, 256>>>(A, B, C, M, N, K, bias, resid, rowscale, rowidx, seg, epi);
}

extern "C" void kernel_launch(void* const* d_in, const int* in_sizes, int n_in,
                              void* d_out, int out_size) {
    const float* x    = (const float*)d_in[0];
    const float* n1w  = (const float*)d_in[1];
    const float* n2w  = (const float*)d_in[2];
    const float* kvnw = (const float*)d_in[3];
    const float* Wq   = (const float*)d_in[4];
    const float* Wkva = (const float*)d_in[5];
    const float* Wkvb = (const float*)d_in[6];
    const float* Wo   = (const float*)d_in[7];
    const float* Wiq  = (const float*)d_in[8];
    const float* Wik  = (const float*)d_in[9];
    const float* Wiw  = (const float*)d_in[10];
    const float* Wr   = (const float*)d_in[11];
    const float* W1   = (const float*)d_in[12];
    const float* b1   = (const float*)d_in[13];
    const float* W2   = (const float*)d_in[14];
    const float* b2   = (const float*)d_in[15];

    float* out     = (float*)d_out;
    float* out_x   = out;
    float* out_aux = out + (size_t)cS * cD;
    float* out_idx = out + (size_t)cS * cD + 1;

    void* pv;
    cudaGetSymbolAddress(&pv, g_h);      float* ph     = (float*)pv;
    cudaGetSymbolAddress(&pv, g_q);      float* pq     = (float*)pv;
    cudaGetSymbolAddress(&pv, g_ckv);    float* pckv   = (float*)pv;
    cudaGetSymbolAddress(&pv, g_c);      float* pc     = (float*)pv;
    cudaGetSymbolAddress(&pv, g_kv);     float* pkv    = (float*)pv;
    cudaGetSymbolAddress(&pv, g_krope);  float* pkr    = (float*)pv;
    cudaGetSymbolAddress(&pv, g_qi);     float* pqi    = (float*)pv;
    cudaGetSymbolAddress(&pv, g_ki);     float* pki    = (float*)pv;
    cudaGetSymbolAddress(&pv, g_wgt);    float* pwgt   = (float*)pv;
    cudaGetSymbolAddress(&pv, g_topk);   int*   ptopk  = (int*)pv;
    cudaGetSymbolAddress(&pv, g_att);    float* patt   = (float*)pv;
    cudaGetSymbolAddress(&pv, g_x2);     float* px2    = (float*)pv;
    cudaGetSymbolAddress(&pv, g_h2);     float* ph2    = (float*)pv;
    cudaGetSymbolAddress(&pv, g_logits); float* plog   = (float*)pv;
    cudaGetSymbolAddress(&pv, g_probs);  float* pprob  = (float*)pv;
    cudaGetSymbolAddress(&pv, g_gidx);   int*   pgidx  = (int*)pv;
    cudaGetSymbolAddress(&pv, g_gval);   float* pgval  = (float*)pv;
    cudaGetSymbolAddress(&pv, g_cnt);    int*   pcnt   = (int*)pv;
    cudaGetSymbolAddress(&pv, g_fill);   int*   pfill  = (int*)pv;
    cudaGetSymbolAddress(&pv, g_seg);    int*   pseg   = (int*)pv;
    cudaGetSymbolAddress(&pv, g_perm);   int*   pperm  = (int*)pv;
    cudaGetSymbolAddress(&pv, g_pgate);  float* ppg    = (float*)pv;
    cudaGetSymbolAddress(&pv, g_slot);   int*   pslot  = (int*)pv;
    cudaGetSymbolAddress(&pv, g_hid);    float* phid   = (float*)pv;
    cudaGetSymbolAddress(&pv, g_eout);   float* peout  = (float*)pv;

    // 1) h = rms(x)
    rms_kernel<<<cS, 256>>>(x, cD, n1w, ph, cD, cD);
    // 2) q = h @ Wq
    gemm(ph, Wq, pq, cS, cQD, cD, nullptr, nullptr, nullptr, nullptr, nullptr, 0);
    // 3) ckv = h @ Wkva
    gemm(ph, Wkva, pckv, cS, cR + cDR, cD, nullptr, nullptr, nullptr, nullptr, nullptr, 0);
    // 4) c = rms(ckv[:, :R])
    rms_kernel<<<cS, 256>>>(pckv, cR + cDR, kvnw, pc, cR, cR);
    // 5) kv = c @ Wkvb
    gemm(pc, Wkvb, pkv, cS, cKVD, cR, nullptr, nullptr, nullptr, nullptr, nullptr, 0);
    // 6) rope
    rope_q_kernel<<<(cS * cH * 32 + 255) / 256, 256>>>(pq);
    rope_k_kernel<<<(cS * 32 + 255) / 256, 256>>>(pckv, pkr);
    // 7) indexer projections
    gemm(ph, Wiq, pqi, cS, cHI * cDI, cD, nullptr, nullptr, nullptr, nullptr, nullptr, 0);
    gemm(ph, Wik, pki, cS, cDI, cD, nullptr, nullptr, nullptr, nullptr, nullptr, 0);
    gemm(ph, Wiw, pwgt, cS, cHI, cD, nullptr, nullptr, nullptr, nullptr, nullptr, 0);
    // 8) idx scores (-> output region)
    idx_kernel<<<dim3(cS / 256, cS), 256>>>(pqi, pki, pwgt, out_idx);
    // 9) top-k select
    topk_fill<<<cKTOP, 256>>>(ptopk);
    topk_radix<<<cS - cKTOP, 256>>>(out_idx, ptopk);
    // 10) sparse attention
    attn_kernel<<<dim3(cS, cH), 256>>>(pq, pkv, pkr, ptopk, patt);
    // 11) x2 = x + att @ Wo
    gemm(patt, Wo, px2, cS, cD, cH * cDV, nullptr, x, nullptr, nullptr, nullptr, 1);
    // 12) h2 = rms(x2)
    rms_kernel<<<cS, 256>>>(px2, cD, n2w, ph2, cD, cD);
    // 13) router logits
    gemm(ph2, Wr, plog, cS, cE, cD, nullptr, nullptr, nullptr, nullptr, nullptr, 0);
    // 14) router softmax/top2/count
    reset_kernel<<<1, 32>>>(pcnt);
    router_kernel<<<(cS + 255) / 256, 256>>>(plog, pprob, pgidx, pgval, pcnt);
    seg_kernel<<<1, 32>>>(pcnt, pseg, pfill);
    place_kernel<<<(cS + 255) / 256, 256>>>(pgidx, pgval, pseg, pfill, pperm, ppg, pslot);
    // 15) MoE expert GEMMs (gathered rows, segment-dynamic M)
    for (int e = 0; e < cE; e++) {
        gemm(ph2, W1 + (size_t)e * cD * cDFF, phid, cS, cDFF, cD,
             b1 + (size_t)e * cDFF, nullptr, nullptr, pperm, pseg + 2 * e, 2);
        gemm(phid, W2 + (size_t)e * cDFF * cD, peout, cS, cD, cDFF,
             b2 + (size_t)e * cD, nullptr, ppg, nullptr, pseg + 2 * e, 3);
    }
    // 16) final residual combine -> output x
    combine_kernel<<<(cS * cD + 255) / 256, 256>>>(px2, peout, pslot, out_x);
    // 17) aux loss -> output scalar
    aux_kernel<<<1, 256>>>(pprob, pcnt, out_aux);
}